// round 2
// baseline (speedup 1.0000x reference)
#include <cuda_runtime.h>
#include <math.h>

#define BB  8
#define SS  8192
#define IND 128
#define DD  64
#define NT  256   // 8 warps = 8 batch rows

// SMEM floats: M1T(8192) WrT(8192) M2T/M3T/P1T/P2T/P3T/pp1/pp2/pp3 (8*4096)
#define SMEM_FLOATS (2 * IND * DD + 8 * DD * DD)
#define SMEM_BYTES  (SMEM_FLOATS * 4)

// 64x64 matvec: out_i = sum_j Wt[j][i] * v_j, vector held in 2 regs/lane
// (v0 <-> j = lane, v1 <-> j = lane+32), broadcast via shfl.
__device__ __forceinline__ void matvec64(const float* __restrict__ Wt,
                                         float v0, float v1,
                                         int i0, int i1,
                                         float& o0, float& o1) {
    float acc0 = 0.f, acc1 = 0.f;
#pragma unroll 8
    for (int j2 = 0; j2 < 32; j2++) {
        float a0 = __shfl_sync(0xffffffffu, v0, j2);
        float a1 = __shfl_sync(0xffffffffu, v1, j2);
        const float* p = Wt + j2 * DD;
        acc0 = fmaf(p[i0], a0, acc0);
        acc1 = fmaf(p[i1], a0, acc1);
        p += 32 * DD;
        acc0 = fmaf(p[i0], a1, acc0);
        acc1 = fmaf(p[i1], a1, acc1);
    }
    o0 = acc0; o1 = acc1;
}

// LayerNorm over the 64 values spread across the warp (2 per lane).
__device__ __forceinline__ void ln64(float xt0, float xt1,
                                     float ga, float gb, float ba, float bb,
                                     float& y0, float& y1) {
    float sum = xt0 + xt1;
#pragma unroll
    for (int o = 16; o > 0; o >>= 1) sum += __shfl_xor_sync(0xffffffffu, sum, o);
    float mu = sum * 0.015625f;
    float d0 = xt0 - mu, d1 = xt1 - mu;
    float sq = fmaf(d0, d0, d1 * d1);
#pragma unroll
    for (int o = 16; o > 0; o >>= 1) sq += __shfl_xor_sync(0xffffffffu, sq, o);
    float rs = rsqrtf(fmaf(sq, 0.015625f, 1e-5f));
    y0 = fmaf(d0 * rs, ga, ba);
    y1 = fmaf(d1 * rs, gb, bb);
}

__global__ __launch_bounds__(NT, 1)
void hier_fused(const float* __restrict__ seq,
                const float* __restrict__ M1, const float* __restrict__ P1,
                const float* __restrict__ g1, const float* __restrict__ b1,
                const float* __restrict__ Wr1,
                const float* __restrict__ M2, const float* __restrict__ P2,
                const float* __restrict__ g2, const float* __restrict__ b2,
                const float* __restrict__ M3, const float* __restrict__ P3,
                const float* __restrict__ g3, const float* __restrict__ b3,
                float* __restrict__ out)
{
    extern __shared__ float sm[];
    float* sM1T = sm;                       // [j][i] 128x64
    float* sWrT = sM1T + IND * DD;          // 128x64
    float* sM2T = sWrT + IND * DD;          // 64x64
    float* sM3T = sM2T + DD * DD;
    float* sP1T = sM3T + DD * DD;
    float* sP2T = sP1T + DD * DD;
    float* sP3T = sP2T + DD * DD;
    float* pp1  = sP3T + DD * DD;           // per-s: P ∘ phi, [j][i]
    float* pp2  = pp1 + DD * DD;
    float* pp3  = pp2 + DD * DD;

    const int tid = threadIdx.x;
    const int w = tid >> 5;      // warp id == batch row b
    const int l = tid & 31;
    const int i0 = l, i1 = l + 32;

    // ---- preload weights (transposed) into SMEM, once per block ----
    for (int idx = tid; idx < IND * DD; idx += NT) {
        int i = idx >> 7, j = idx & 127;    // idx = i*128 + j (coalesced read)
        sM1T[j * DD + i] = M1[idx];
        sWrT[j * DD + i] = Wr1[idx];
    }
    for (int idx = tid; idx < DD * DD; idx += NT) {
        int i = idx >> 6, j = idx & 63;
        sM2T[j * DD + i] = M2[idx];
        sM3T[j * DD + i] = M3[idx];
        sP1T[j * DD + i] = P1[idx];
        sP2T[j * DD + i] = P2[idx];
        sP3T[j * DD + i] = P3[idx];
    }
    const float G1a = g1[i0], G1b = g1[i1], B1a = b1[i0], B1b = b1[i1];
    const float G2a = g2[i0], G2b = g2[i1], B2a = b2[i0], B2b = b2[i1];
    const float G3a = g3[i0], G3b = g3[i1], B3a = b3[i0], B3b = b3[i1];
    __syncthreads();

    // phi-build mapping: thread covers i = tid&63, j = (tid>>6)*16 + m
    const int ci  = tid & 63;
    const int cjb = (tid >> 6) << 4;
    const float  TWO_PI_F = 6.28318548202514648438f;   // fl32(2*pi), matches jax
    const double INV_2PI  = 0.15915494309189535;
    const double TWO_PI_D = 6.283185307179586;

    for (int s = blockIdx.x; s < SS; s += gridDim.x) {
        // input vector for this warp's batch row (coalesced, held in regs)
        const float* xp = seq + ((size_t)w * SS + (size_t)s) * IND;
        float x0 = xp[l], x1 = xp[l + 32], x2 = xp[l + 64], x3 = xp[l + 96];

        // ---- build pp = P * cos(2*pi*s/period), transposed [j][i] ----
        {
            const float ts = __fmul_rn(TWO_PI_F, (float)s);  // fl(2pi*s), jax order
#pragma unroll
            for (int m = 0; m < 16; m++) {
                int j = cjb + m;
                int k = ci * DD + j;                  // periods[i][j] = i*64+j+2
                float u = __fdiv_rn(ts, (float)(k + 2));  // exact jax fp32 rounding
                // exact range reduction in double, then cos on |r|<=pi
                double ud = (double)u;
                double q  = rint(ud * INV_2PI);
                float  r  = (float)__fma_rn(q, -TWO_PI_D, ud);
                float  c  = cosf(r);
                int o = j * DD + ci;
                pp1[o] = sP1T[o] * c;
                pp2[o] = sP2T[o] * c;
                pp3[o] = sP3T[o] * c;
            }
        }
        __syncthreads();

        // ================= layer 1 (128 -> 64) =================
        float xt0 = 0.f, xt1 = 0.f, rr0 = 0.f, rr1 = 0.f;
#pragma unroll 8
        for (int j2 = 0; j2 < 32; j2++) {
            float a0 = __shfl_sync(0xffffffffu, x0, j2);
            float a1 = __shfl_sync(0xffffffffu, x1, j2);
            float a2 = __shfl_sync(0xffffffffu, x2, j2);
            float a3 = __shfl_sync(0xffffffffu, x3, j2);
            const float* m = sM1T + j2 * DD;
            const float* r = sWrT + j2 * DD;
            xt0 = fmaf(m[i0], a0, xt0);  xt1 = fmaf(m[i1], a0, xt1);
            rr0 = fmaf(r[i0], a0, rr0);  rr1 = fmaf(r[i1], a0, rr1);
            m += 32 * DD; r += 32 * DD;
            xt0 = fmaf(m[i0], a1, xt0);  xt1 = fmaf(m[i1], a1, xt1);
            rr0 = fmaf(r[i0], a1, rr0);  rr1 = fmaf(r[i1], a1, rr1);
            m += 32 * DD; r += 32 * DD;
            xt0 = fmaf(m[i0], a2, xt0);  xt1 = fmaf(m[i1], a2, xt1);
            rr0 = fmaf(r[i0], a2, rr0);  rr1 = fmaf(r[i1], a2, rr1);
            m += 32 * DD; r += 32 * DD;
            xt0 = fmaf(m[i0], a3, xt0);  xt1 = fmaf(m[i1], a3, xt1);
            rr0 = fmaf(r[i0], a3, rr0);  rr1 = fmaf(r[i1], a3, rr1);
        }
        float y0, y1;
        ln64(xt0, xt1, G1a, G1b, B1a, B1b, y0, y1);
        float n0, n1;
        matvec64(pp1, y0, y1, i0, i1, n0, n1);
        float z0 = n0 + rr0, z1 = n1 + rr1;       // x1 = Nk + seq@Wr1^T

        // ================= layer 2 (64 -> 64) =================
        matvec64(sM2T, z0, z1, i0, i1, xt0, xt1);
        ln64(xt0, xt1, G2a, G2b, B2a, B2b, y0, y1);
        matvec64(pp2, y0, y1, i0, i1, n0, n1);
        z0 = n0 + z0;  z1 = n1 + z1;              // identity residual

        // ================= layer 3 (64 -> 64) =================
        matvec64(sM3T, z0, z1, i0, i1, xt0, xt1);
        ln64(xt0, xt1, G3a, G3b, B3a, B3b, y0, y1);
        matvec64(pp3, y0, y1, i0, i1, n0, n1);
        z0 = n0 + z0;  z1 = n1 + z1;

        // ---- store (coalesced) ----
        float* op = out + ((size_t)w * SS + (size_t)s) * DD;
        op[i0] = z0;
        op[i1] = z1;

        __syncthreads();   // protect pp before next iteration overwrites
    }
}

extern "C" void kernel_launch(void* const* d_in, const int* in_sizes, int n_in,
                              void* d_out, int out_size) {
    const float* seq = (const float*)d_in[0];
    const float* M1  = (const float*)d_in[1];
    const float* P1  = (const float*)d_in[2];
    const float* g1  = (const float*)d_in[3];
    const float* b1  = (const float*)d_in[4];
    const float* Wr1 = (const float*)d_in[5];
    const float* M2  = (const float*)d_in[6];
    const float* P2  = (const float*)d_in[7];
    const float* g2  = (const float*)d_in[8];
    const float* b2  = (const float*)d_in[9];
    const float* M3  = (const float*)d_in[10];
    const float* P3  = (const float*)d_in[11];
    const float* g3  = (const float*)d_in[12];
    const float* b3  = (const float*)d_in[13];
    float* out = (float*)d_out;

    cudaFuncSetAttribute(hier_fused,
                         cudaFuncAttributeMaxDynamicSharedMemorySize, SMEM_BYTES);

    int dev = 0, sms = 148;
    if (cudaGetDevice(&dev) == cudaSuccess) {
        int v = 0;
        if (cudaDeviceGetAttribute(&v, cudaDevAttrMultiProcessorCount, dev) == cudaSuccess
            && v > 0) sms = v;
    }
    if (sms > SS) sms = SS;

    hier_fused<<<sms, NT, SMEM_BYTES>>>(seq, M1, P1, g1, b1, Wr1,
                                        M2, P2, g2, b2, M3, P3, g3, b3, out);
}

// round 3
// speedup vs baseline: 2.3439x; 2.3439x over previous
#include <cuda_runtime.h>
#include <math.h>

#define SS  8192
#define IND 128
#define DD  64
#define NT  512            // 16 warps, each warp owns one position (all 8 batches)
#define WARPS (NT/32)

#define W_FLOATS (2*IND*DD + 5*DD*DD)          // 36864 floats static weights
#define STAGE_PER_WARP 1024                    // x/y/z staging, reused
#define SMEM_FLOATS (W_FLOATS + WARPS*STAGE_PER_WARP)
#define SMEM_BYTES  (SMEM_FLOATS*4)            // 212992 B

typedef unsigned long long ull;

// ---- packed f32x2 helpers (sm_100) ----
__device__ __forceinline__ ull dup2(float a){ ull r; asm("mov.b64 %0, {%1,%1};":"=l"(r):"f"(a)); return r; }
__device__ __forceinline__ ull pk2(float x,float y){ ull r; asm("mov.b64 %0, {%1,%2};":"=l"(r):"f"(x),"f"(y)); return r; }
__device__ __forceinline__ float2 up2(ull v){ float2 f; asm("mov.b64 {%0,%1}, %2;":"=f"(f.x),"=f"(f.y):"l"(v)); return f; }
__device__ __forceinline__ void fma2(ull&d, ull a, ull b){ asm("fma.rn.f32x2 %0, %1, %2, %0;":"+l"(d):"l"(a),"l"(b)); }
__device__ __forceinline__ ull mul2(ull a, ull b){ ull r; asm("mul.rn.f32x2 %0, %1, %2;":"=l"(r):"l"(a),"l"(b)); return r; }
__device__ __forceinline__ ull add2(ull a, ull b){ ull r; asm("add.rn.f32x2 %0, %1, %2;":"=l"(r):"l"(a),"l"(b)); return r; }

// cos(fl32(ts/p)) matching JAX fp32 rounding: correctly-rounded div, then
// all-fp32 Cody-Waite 3-term reduction (q<=4096, splits chosen so q*hi and
// q*mid are exact), then hardware cos on |r|<=pi (~4e-7 abs).
#define CW_HI  6.28125f
#define CW_MID 1.93500518798828125e-3f   /* 2029 * 2^-20, 12-bit significand */
#define CW_LO  3.0199159819567e-7f
__device__ __forceinline__ float pcosf(float ts, float p){
    float u = __fdiv_rn(ts, p);                       // exact jax value
    float q = rintf(u * 0.15915494309189535f);
    float r = fmaf(q, -CW_HI,  u);
    r       = fmaf(q, -CW_MID, r);
    r       = fmaf(q, -CW_LO,  r);
    return __cosf(r);
}

// LayerNorm over 64 values (2/lane, packed) for 8 batches, ILP-interleaved.
__device__ __forceinline__ void ln8(ull v[8], float ga, float gb, float ba, float bb){
    float2 xx[8]; float sx[8], sq[8];
#pragma unroll
    for (int b=0;b<8;b++){ xx[b]=up2(v[b]); sx[b]=xx[b].x+xx[b].y; }
#pragma unroll
    for (int o=16;o;o>>=1){
#pragma unroll
        for (int b=0;b<8;b++) sx[b] += __shfl_xor_sync(0xffffffffu, sx[b], o);
    }
#pragma unroll
    for (int b=0;b<8;b++){
        float mu = sx[b]*0.015625f;
        xx[b].x -= mu; xx[b].y -= mu;
        sq[b] = fmaf(xx[b].x, xx[b].x, xx[b].y*xx[b].y);
    }
#pragma unroll
    for (int o=16;o;o>>=1){
#pragma unroll
        for (int b=0;b<8;b++) sq[b] += __shfl_xor_sync(0xffffffffu, sq[b], o);
    }
#pragma unroll
    for (int b=0;b<8;b++){
        float rs = rsqrtf(fmaf(sq[b], 0.015625f, 1e-5f));
        v[b] = pk2(fmaf(xx[b].x*rs, ga, ba), fmaf(xx[b].y*rs, gb, bb));
    }
}

// acc[b] (packed i-pair) += Wt[j][i-pair] * S[b][j]   (Wt transposed [j][i])
__device__ __forceinline__ void mm64(const float* __restrict__ Wt,
                                     const float* __restrict__ S,
                                     int l2, ull acc[8]){
#pragma unroll 4
    for (int j=0;j<DD;j+=2){
        ull w0 = *(const ull*)(Wt + j*DD + l2);
        ull w1 = *(const ull*)(Wt + (j+1)*DD + l2);
#pragma unroll
        for (int b=0;b<8;b++){
            float2 av = *(const float2*)(S + b*DD + j);
            fma2(acc[b], w0, dup2(av.x));
            fma2(acc[b], w1, dup2(av.y));
        }
    }
}

// N-matvec with on-the-fly phase: acc[b] += (P[i][j]*cos(ts/(i*64+j+2))) * S[b][j]
__device__ __forceinline__ void nmv64(const float* __restrict__ Pt,
                                      const float* __restrict__ S,
                                      int l2, float ts, float pbase, ull acc[8]){
    float pf0 = pbase;          // period for i0 = 2l  : 128l + 2 + j
    float pf1 = pbase + 64.f;   // period for i1 = 2l+1
#pragma unroll 2
    for (int j=0;j<DD;j+=2){
        float c00 = pcosf(ts, pf0);
        float c01 = pcosf(ts, pf1);
        float c10 = pcosf(ts, pf0 + 1.f);
        float c11 = pcosf(ts, pf1 + 1.f);
        pf0 += 2.f; pf1 += 2.f;
        ull pw0 = mul2(*(const ull*)(Pt + j*DD + l2),     pk2(c00, c01));
        ull pw1 = mul2(*(const ull*)(Pt + (j+1)*DD + l2), pk2(c10, c11));
#pragma unroll
        for (int b=0;b<8;b++){
            float2 av = *(const float2*)(S + b*DD + j);
            fma2(acc[b], pw0, dup2(av.x));
            fma2(acc[b], pw1, dup2(av.y));
        }
    }
}

__global__ __launch_bounds__(NT, 1)
void hier_fused2(const float* __restrict__ seq,
                 const float* __restrict__ M1, const float* __restrict__ P1,
                 const float* __restrict__ g1, const float* __restrict__ b1,
                 const float* __restrict__ Wr1,
                 const float* __restrict__ M2, const float* __restrict__ P2,
                 const float* __restrict__ g2, const float* __restrict__ b2,
                 const float* __restrict__ M3, const float* __restrict__ P3,
                 const float* __restrict__ g3, const float* __restrict__ b3,
                 float* __restrict__ out)
{
    extern __shared__ float sm[];
    float* sM1T = sm;                    // [j][i] 128x64
    float* sWrT = sM1T + IND*DD;         // 128x64
    float* sM2T = sWrT + IND*DD;         // 64x64 each
    float* sM3T = sM2T + DD*DD;
    float* sP1T = sM3T + DD*DD;
    float* sP2T = sP1T + DD*DD;
    float* sP3T = sP2T + DD*DD;
    float* stage = sP3T + DD*DD;

    const int tid = threadIdx.x;
    const int wid = tid >> 5;
    const int l   = tid & 31;
    const int l2  = 2*l;

    float* X = stage + wid*STAGE_PER_WARP;   // [b][128] input, reused as Y
    float* Y = X;                            // [b][64]
    float* Z = X + 8*DD;                     // [b][64]

    // ---- preload weights transposed into SMEM ----
    for (int idx = tid; idx < IND*DD; idx += NT){
        int i = idx >> 7, j = idx & 127;
        sM1T[j*DD + i] = M1[idx];
        sWrT[j*DD + i] = Wr1[idx];
    }
    for (int idx = tid; idx < DD*DD; idx += NT){
        int i = idx >> 6, j = idx & 63;
        sM2T[j*DD + i] = M2[idx];
        sM3T[j*DD + i] = M3[idx];
        sP1T[j*DD + i] = P1[idx];
        sP2T[j*DD + i] = P2[idx];
        sP3T[j*DD + i] = P3[idx];
    }
    const float G1a=g1[l2], G1b=g1[l2+1], B1a=b1[l2], B1b=b1[l2+1];
    const float G2a=g2[l2], G2b=g2[l2+1], B2a=b2[l2], B2b=b2[l2+1];
    const float G3a=g3[l2], G3b=g3[l2+1], B3a=b3[l2], B3b=b3[l2+1];
    __syncthreads();

    const float pbase  = (float)(128*l + 2);
    const int   stride = gridDim.x * WARPS;

    for (int s = blockIdx.x*WARPS + wid; s < SS; s += stride){
        const float ts = __fmul_rn(6.2831853071795862f, (float)s);

        // ---- load input (8 batches x 128) into staging ----
#pragma unroll
        for (int b=0;b<8;b++){
            float4 v = *(const float4*)(seq + ((size_t)b*SS + s)*IND + 4*l);
            *(float4*)(X + b*IND + 4*l) = v;
        }
        __syncwarp();

        // ================= layer 1: xt = x@M1T, rr = x@WrT =================
        ull xt[8], rr[8];
#pragma unroll
        for (int b=0;b<8;b++){ xt[b]=0ull; rr[b]=0ull; }
#pragma unroll 2
        for (int j=0;j<IND;j+=2){
            ull m0 = *(const ull*)(sM1T + j*DD + l2);
            ull m1 = *(const ull*)(sM1T + (j+1)*DD + l2);
            ull r0 = *(const ull*)(sWrT + j*DD + l2);
            ull r1 = *(const ull*)(sWrT + (j+1)*DD + l2);
#pragma unroll
            for (int b=0;b<8;b++){
                float2 av = *(const float2*)(X + b*IND + j);
                ull a0 = dup2(av.x), a1 = dup2(av.y);
                fma2(xt[b], m0, a0);  fma2(rr[b], r0, a0);
                fma2(xt[b], m1, a1);  fma2(rr[b], r1, a1);
            }
        }
        ln8(xt, G1a, G1b, B1a, B1b);
        __syncwarp();
#pragma unroll
        for (int b=0;b<8;b++) *(ull*)(Y + b*DD + l2) = xt[b];
        __syncwarp();
        ull nn[8];
#pragma unroll
        for (int b=0;b<8;b++) nn[b]=0ull;
        nmv64(sP1T, Y, l2, ts, pbase, nn);
        ull z[8];
#pragma unroll
        for (int b=0;b<8;b++) z[b] = add2(nn[b], rr[b]);

        // ================= layer 2 =================
        __syncwarp();
#pragma unroll
        for (int b=0;b<8;b++) *(ull*)(Z + b*DD + l2) = z[b];
        __syncwarp();
#pragma unroll
        for (int b=0;b<8;b++) xt[b]=0ull;
        mm64(sM2T, Z, l2, xt);
        ln8(xt, G2a, G2b, B2a, B2b);
        __syncwarp();
#pragma unroll
        for (int b=0;b<8;b++) *(ull*)(Y + b*DD + l2) = xt[b];
        __syncwarp();
#pragma unroll
        for (int b=0;b<8;b++) nn[b]=0ull;
        nmv64(sP2T, Y, l2, ts, pbase, nn);
#pragma unroll
        for (int b=0;b<8;b++) z[b] = add2(nn[b], z[b]);

        // ================= layer 3 =================
        __syncwarp();
#pragma unroll
        for (int b=0;b<8;b++) *(ull*)(Z + b*DD + l2) = z[b];
        __syncwarp();
#pragma unroll
        for (int b=0;b<8;b++) xt[b]=0ull;
        mm64(sM3T, Z, l2, xt);
        ln8(xt, G3a, G3b, B3a, B3b);
        __syncwarp();
#pragma unroll
        for (int b=0;b<8;b++) *(ull*)(Y + b*DD + l2) = xt[b];
        __syncwarp();
#pragma unroll
        for (int b=0;b<8;b++) nn[b]=0ull;
        nmv64(sP3T, Y, l2, ts, pbase, nn);
#pragma unroll
        for (int b=0;b<8;b++) z[b] = add2(nn[b], z[b]);

        // ---- store (8 x STG.64, coalesced per batch) ----
#pragma unroll
        for (int b=0;b<8;b++)
            *(ull*)(out + ((size_t)b*SS + s)*DD + l2) = z[b];
    }
}

extern "C" void kernel_launch(void* const* d_in, const int* in_sizes, int n_in,
                              void* d_out, int out_size) {
    const float* seq = (const float*)d_in[0];
    const float* M1  = (const float*)d_in[1];
    const float* P1  = (const float*)d_in[2];
    const float* g1  = (const float*)d_in[3];
    const float* b1  = (const float*)d_in[4];
    const float* Wr1 = (const float*)d_in[5];
    const float* M2  = (const float*)d_in[6];
    const float* P2  = (const float*)d_in[7];
    const float* g2  = (const float*)d_in[8];
    const float* b2  = (const float*)d_in[9];
    const float* M3  = (const float*)d_in[10];
    const float* P3  = (const float*)d_in[11];
    const float* g3  = (const float*)d_in[12];
    const float* b3  = (const float*)d_in[13];
    float* out = (float*)d_out;

    cudaFuncSetAttribute(hier_fused2,
                         cudaFuncAttributeMaxDynamicSharedMemorySize, SMEM_BYTES);

    int dev = 0, sms = 148;
    if (cudaGetDevice(&dev) == cudaSuccess) {
        int v = 0;
        if (cudaDeviceGetAttribute(&v, cudaDevAttrMultiProcessorCount, dev) == cudaSuccess
            && v > 0) sms = v;
    }

    hier_fused2<<<sms, NT, SMEM_BYTES>>>(seq, M1, P1, g1, b1, Wr1,
                                         M2, P2, g2, b2, M3, P3, g3, b3, out);
}